// round 9
// baseline (speedup 1.0000x reference)
#include <cuda_runtime.h>

#define BATCH 256

// ---------------- device scratch (no allocations allowed) ----------------
// Winograd-transformed weights: [o][c][g][16]
__device__ float g_W1[8  * 3  * 7 * 16];   // 2688
__device__ float g_W2[16 * 8  * 7 * 16];   // 12544
__device__ float g_W3[32 * 16 * 7 * 16];   // 57344
__device__ float g_out1[BATCH * 8  * 16 * 16];
__device__ float g_out2[BATCH * 16 * 8 * 8];
__device__ float g_out3[BATCH * 32 * 4 * 4];

// ---------------- spline/silu feature expansion ----------------
__device__ __forceinline__ void compute_phi(float v, float* phi) {
    const float h = 2.0f / 3.0f;
    float b[9];
#pragma unroll
    for (int i = 0; i < 9; i++) {
        float t0 = (i - 3) * h - 1.0f;
        float t1 = (i - 2) * h - 1.0f;
        b[i] = (v >= t0 && v < t1) ? 1.0f : 0.0f;
    }
#pragma unroll
    for (int j = 1; j <= 3; j++) {
        float inv = 1.0f / (j * h);
#pragma unroll
        for (int i = 0; i + j < 9; i++) {
            float ti  = (i - 3) * h - 1.0f;
            float tj1 = (i + j - 2) * h - 1.0f;
            b[i] = (v - ti) * inv * b[i] + (tj1 - v) * inv * b[i + 1];
        }
    }
    phi[0] = v / (1.0f + __expf(-v));
#pragma unroll
    for (int g = 0; g < 6; g++) phi[g + 1] = b[g];
}

// ---------------- prep: fold scaler, Winograd-transform weights ----------------
// U = G w G^T, G = [[1,0,0],[.5,.5,.5],[.5,-.5,.5],[0,0,1]]
template <int O, int C>
__device__ __forceinline__ void fold_wino(float* Wd, int i, const float* __restrict__ bw,
                                          const float* __restrict__ sw,
                                          const float* __restrict__ sc) {
    // i over (o, c, g)
    int g = i % 7;
    int c = (i / 7) % C;
    int o = i / (7 * C);
    constexpr int F = C * 9;
    float w[3][3];
#pragma unroll
    for (int kh = 0; kh < 3; kh++)
#pragma unroll
        for (int kw = 0; kw < 3; kw++) {
            int f = c * 9 + kh * 3 + kw;
            w[kh][kw] = (g == 0) ? bw[o * F + f]
                                 : sw[(o * F + f) * 6 + (g - 1)] * sc[o * F + f];
        }
    // T = G w  (4x3)
    float T[4][3];
#pragma unroll
    for (int k = 0; k < 3; k++) {
        T[0][k] = w[0][k];
        T[1][k] = 0.5f * (w[0][k] + w[1][k] + w[2][k]);
        T[2][k] = 0.5f * (w[0][k] - w[1][k] + w[2][k]);
        T[3][k] = w[2][k];
    }
    // U = T G^T  (4x4)
    float* U = &Wd[((o * C + c) * 7 + g) * 16];
#pragma unroll
    for (int r = 0; r < 4; r++) {
        U[r * 4 + 0] = T[r][0];
        U[r * 4 + 1] = 0.5f * (T[r][0] + T[r][1] + T[r][2]);
        U[r * 4 + 2] = 0.5f * (T[r][0] - T[r][1] + T[r][2]);
        U[r * 4 + 3] = T[r][2];
    }
}

#define NOCG1 (8 * 3 * 7)     // 168
#define NOCG2 (16 * 8 * 7)    // 896
#define NOCG3 (32 * 16 * 7)   // 3584
#define NPREP (NOCG1 + NOCG2 + NOCG3)

__global__ void prep_all(
    const float* __restrict__ c1bw, const float* __restrict__ c1sw, const float* __restrict__ c1sc,
    const float* __restrict__ c2bw, const float* __restrict__ c2sw, const float* __restrict__ c2sc,
    const float* __restrict__ c3bw, const float* __restrict__ c3sw, const float* __restrict__ c3sc)
{
    int i = blockIdx.x * blockDim.x + threadIdx.x;
    if (i < NOCG1) {
        fold_wino<8, 3>(g_W1, i, c1bw, c1sw, c1sc);
    } else if (i < NOCG1 + NOCG2) {
        fold_wino<16, 8>(g_W2, i - NOCG1, c2bw, c2sw, c2sc);
    } else if (i < NPREP) {
        fold_wino<32, 16>(g_W3, i - NOCG1 - NOCG2, c3bw, c3sw, c3sc);
    }
}

// ---------------- Winograd conv inner loop over CT channels ----------------
// acc[o][16] accumulates in the transform (M) domain.
template <int CT, int OT, int Yd, int Xd>
__device__ __forceinline__ void conv_body_wino(
    const float* E, const float* __restrict__ Wg, float acc[OT][16],
    int c0, int pr, int px, int og_base, int C_total)
{
#pragma unroll 1
    for (int cc = 0; cc < CT; cc++) {
        int c = c0 + cc;
#pragma unroll
        for (int g = 0; g < 7; g++) {
            float e[4][4];
            const int base = ((c * Yd + 2 * pr) * 7 + g) * Xd + 2 * px;
#pragma unroll
            for (int dy = 0; dy < 4; dy++) {
                const float2* r = reinterpret_cast<const float2*>(&E[base + dy * 7 * Xd]);
                float2 a = r[0], b2 = r[1];
                e[dy][0] = a.x; e[dy][1] = a.y; e[dy][2] = b2.x; e[dy][3] = b2.y;
            }
            // input transform V = B^T e B (rows then cols)
            float t[4][4];
#pragma unroll
            for (int r = 0; r < 4; r++) {
                t[r][0] = e[r][0] - e[r][2];
                t[r][1] = e[r][1] + e[r][2];
                t[r][2] = e[r][2] - e[r][1];
                t[r][3] = e[r][1] - e[r][3];
            }
            float V[16];
#pragma unroll
            for (int k = 0; k < 4; k++) {
                V[0 * 4 + k]  = t[0][k] - t[2][k];
                V[1 * 4 + k]  = t[1][k] + t[2][k];
                V[2 * 4 + k]  = t[2][k] - t[1][k];
                V[3 * 4 + k]  = t[1][k] - t[3][k];
            }
#pragma unroll
            for (int o = 0; o < OT; o++) {
                const float4* uv = reinterpret_cast<const float4*>(
                    &Wg[(((og_base + o * C_total) + c) * 7 + g) * 16]);
                float4 u0 = __ldg(&uv[0]);
                float4 u1 = __ldg(&uv[1]);
                float4 u2 = __ldg(&uv[2]);
                float4 u3 = __ldg(&uv[3]);
                float u[16] = {u0.x, u0.y, u0.z, u0.w, u1.x, u1.y, u1.z, u1.w,
                               u2.x, u2.y, u2.z, u2.w, u3.x, u3.y, u3.z, u3.w};
#pragma unroll
                for (int k = 0; k < 16; k++) acc[o][k] += V[k] * u[k];
            }
        }
    }
}

// output transform: M(4x4) -> Y(2x2) = A^T M A
__device__ __forceinline__ void wino_out(const float* M, float y[4]) {
    float s[2][4];
#pragma unroll
    for (int k = 0; k < 4; k++) {
        s[0][k] = M[0 * 4 + k] + M[1 * 4 + k] + M[2 * 4 + k];
        s[1][k] = M[1 * 4 + k] - M[2 * 4 + k] - M[3 * 4 + k];
    }
    y[0] = s[0][0] + s[0][1] + s[0][2];
    y[1] = s[0][1] - s[0][2] - s[0][3];
    y[2] = s[1][0] + s[1][1] + s[1][2];
    y[3] = s[1][1] - s[1][2] - s[1][3];
}

// ---------------- phi expansion of a strip into smem ----------------
template <int C, int H, int W, int SR, int THREADS>
__device__ __forceinline__ void expand_strip(
    const float* __restrict__ inb, float* E, int s, int tid)
{
    constexpr int Yd = 2 * SR + 2, Xd = W + 2;
    const int gy0 = 2 * s * SR - 1;
    for (int i = tid; i < C * Yd * Xd; i += THREADS) {
        int x  = i % Xd;
        int ly = (i / Xd) % Yd;
        int c  = i / (Xd * Yd);
        int gy = gy0 + ly;
        float v = 0.0f;
        if (gy >= 0 && gy < H && x >= 1 && x <= W) v = __ldg(&inb[(c * H + gy) * W + x - 1]);
        float phi[7];
        compute_phi(v, phi);
#pragma unroll
        for (int g = 0; g < 7; g++) E[((c * Yd + ly) * 7 + g) * Xd + x] = phi[g];
    }
}

// ---------------- layers 1/2: strip kernel, 64 threads ----------------
template <int C, int H, int W, int O, int OT, int SR>
__global__ void __launch_bounds__(64, 6) kan_layer(
    const float* __restrict__ in, float* __restrict__ out, const float* __restrict__ Wg)
{
    constexpr int PW = W / 2, PH = H / 2;
    constexpr int OG = O / OT;
    constexpr int STRIPS = PH / SR;
    constexpr int Yd = 2 * SR + 2, Xd = W + 2;
    constexpr int THREADS = PW * SR * OG;
    static_assert(THREADS == 64, "block must be 64 threads");

    extern __shared__ float E[];

    const int b   = blockIdx.x / STRIPS;
    const int s   = blockIdx.x % STRIPS;
    const int tid = threadIdx.x;

    expand_strip<C, H, W, SR, THREADS>(in + (size_t)b * C * H * W, E, s, tid);
    __syncthreads();

    const int px = tid % PW;
    const int pr = (tid / PW) % SR;
    const int og = tid / (PW * SR);

    float acc[OT][16];
#pragma unroll
    for (int o = 0; o < OT; o++)
#pragma unroll
        for (int k = 0; k < 16; k++) acc[o][k] = 0.0f;

    conv_body_wino<C, OT, Yd, Xd>(E, Wg, acc, 0, pr, px, og * OT * C, C);

    float* outb = out + (size_t)b * O * PH * PW;
    const int prow = s * SR + pr;
#pragma unroll
    for (int o = 0; o < OT; o++) {
        float y[4];
        wino_out(acc[o], y);
        float m = fmaxf(fmaxf(y[0], y[1]), fmaxf(y[2], y[3]));
        outb[((og * OT + o) * PH + prow) * PW + px] = m;
    }
}

// ---------------- layer 3: channel-split (CS=2), 128 threads ----------------
__global__ void __launch_bounds__(128, 3) kan_layer3(
    const float* __restrict__ in, float* __restrict__ out, const float* __restrict__ Wg)
{
    constexpr int C = 16, H = 8, W = 8, O = 32, OT = 4, SR = 2;
    constexpr int PW = W / 2, PH = H / 2;
    constexpr int OG = O / OT;                 // 8
    constexpr int STRIPS = PH / SR;            // 2
    constexpr int Yd = 2 * SR + 2, Xd = W + 2; // 6, 10
    constexpr int THREADS = 128;
    constexpr int HALF = 64;

    extern __shared__ float E[];               // 16*6*7*10 = 6720 floats

    const int b   = blockIdx.x / STRIPS;
    const int s   = blockIdx.x % STRIPS;
    const int tid = threadIdx.x;

    expand_strip<C, H, W, SR, THREADS>(in + (size_t)b * C * H * W, E, s, tid);
    __syncthreads();

    const int px = tid % PW;
    const int pr = (tid / PW) % SR;
    const int og = (tid / (PW * SR)) % OG;
    const int cs = tid / (PW * SR * OG);

    float acc[OT][16];
#pragma unroll
    for (int o = 0; o < OT; o++)
#pragma unroll
        for (int k = 0; k < 16; k++) acc[o][k] = 0.0f;

    conv_body_wino<8, OT, Yd, Xd>(E, Wg, acc, cs * 8, pr, px, og * OT * C, C);

    // output transform per half (linear), combine Y partials via smem
    float y[OT][4];
#pragma unroll
    for (int o = 0; o < OT; o++) wino_out(acc[o], y[o]);

    __syncthreads();                            // all conv reads of E done
    float* P = E;                               // reuse arena: 64*17 floats
    const int slot = tid % HALF;
    if (cs == 1) {
#pragma unroll
        for (int o = 0; o < OT; o++)
#pragma unroll
            for (int k = 0; k < 4; k++) P[slot * 17 + o * 4 + k] = y[o][k];
    }
    __syncthreads();
    if (cs == 0) {
        float* outb = out + (size_t)b * O * PH * PW;
        const int prow = s * SR + pr;
#pragma unroll
        for (int o = 0; o < OT; o++) {
            float v0 = y[o][0] + P[slot * 17 + o * 4 + 0];
            float v1 = y[o][1] + P[slot * 17 + o * 4 + 1];
            float v2 = y[o][2] + P[slot * 17 + o * 4 + 2];
            float v3 = y[o][3] + P[slot * 17 + o * 4 + 3];
            float m = fmaxf(fmaxf(v0, v1), fmaxf(v2, v3));
            outb[((og * OT + o) * PH + prow) * PW + px] = m;
        }
    }
}

// ---------------- final linear 512 -> 100 (direct linw rows, float4) ----------------
__global__ void __launch_bounds__(128) linear_k(const float* __restrict__ linw,
                                                const float* __restrict__ bias,
                                                float* __restrict__ out) {
    __shared__ float hs[512];
    int b = blockIdx.x;
    for (int i = threadIdx.x; i < 512; i += 128) hs[i] = g_out3[b * 512 + i];
    __syncthreads();
    int j = threadIdx.x;
    if (j < 100) {
        float a = __ldg(&bias[j]);
        const float4* wr = reinterpret_cast<const float4*>(linw + (size_t)j * 512);
        const float4* h4 = reinterpret_cast<const float4*>(hs);
#pragma unroll 8
        for (int f = 0; f < 128; f++) {
            float4 w = __ldg(&wr[f]);
            float4 hv = h4[f];
            a += w.x * hv.x + w.y * hv.y + w.z * hv.z + w.w * hv.w;
        }
        out[(size_t)b * 100 + j] = a;
    }
}

extern "C" void kernel_launch(void* const* d_in, const int* in_sizes, int n_in,
                              void* d_out, int out_size) {
    const float* x     = (const float*)d_in[0];
    const float* c1bw  = (const float*)d_in[1];
    const float* c1sw  = (const float*)d_in[2];
    const float* c1sc  = (const float*)d_in[3];
    const float* c2bw  = (const float*)d_in[4];
    const float* c2sw  = (const float*)d_in[5];
    const float* c2sc  = (const float*)d_in[6];
    const float* c3bw  = (const float*)d_in[7];
    const float* c3sw  = (const float*)d_in[8];
    const float* c3sc  = (const float*)d_in[9];
    const float* linw  = (const float*)d_in[10];
    const float* linb  = (const float*)d_in[11];
    float* out = (float*)d_out;

    static float *p_W1, *p_W2, *p_W3, *p_o1, *p_o2, *p_o3;
    static bool init = false;
    if (!init) {
        cudaGetSymbolAddress((void**)&p_W1, g_W1);
        cudaGetSymbolAddress((void**)&p_W2, g_W2);
        cudaGetSymbolAddress((void**)&p_W3, g_W3);
        cudaGetSymbolAddress((void**)&p_o1, g_out1);
        cudaGetSymbolAddress((void**)&p_o2, g_out2);
        cudaGetSymbolAddress((void**)&p_o3, g_out3);
        init = true;
    }

    prep_all<<<(NPREP + 255) / 256, 256>>>(c1bw, c1sw, c1sc, c2bw, c2sw, c2sc,
                                           c3bw, c3sw, c3sc);

    // L1: C=3 O=8  OT=4 SR=2 -> 64 thr, 8 strips, grid 2048, smem 17136 B
    kan_layer<3, 32, 32, 8, 4, 2><<<BATCH * 8, 64, 3 * 6 * 7 * 34 * 4>>>(x, p_o1, p_W1);
    // L2: C=8 O=16 OT=4 SR=2 -> 64 thr, 4 strips, grid 1024, smem 24192 B
    kan_layer<8, 16, 16, 16, 4, 2><<<BATCH * 4, 64, 8 * 6 * 7 * 18 * 4>>>(p_o1, p_o2, p_W2);
    // L3: C=16 O=32 OT=4 SR=2 CS=2 -> 128 thr, 2 strips, grid 512, smem 26880 B
    kan_layer3<<<BATCH * 2, 128, 16 * 6 * 7 * 10 * 4>>>(p_o2, p_o3, p_W3);

    linear_k<<<BATCH, 128>>>(linw, linb, out);
}

// round 11
// speedup vs baseline: 2.2580x; 2.2580x over previous
#include <cuda_runtime.h>

#define BATCH 256

// ---------------- device scratch (no allocations allowed) ----------------
__device__ float g_W1[8  * 3  * 7 * 12];   // 2016
__device__ float g_W2[16 * 8  * 7 * 12];   // 10752
__device__ float g_W3[32 * 16 * 7 * 12];   // 43008
__device__ float g_out1[BATCH * 8  * 16 * 16];
__device__ float g_out2[BATCH * 16 * 8 * 8];
__device__ float g_out3[BATCH * 32 * 4 * 4];

// ---------------- spline/silu feature expansion ----------------
__device__ __forceinline__ void compute_phi(float v, float* phi) {
    const float h = 2.0f / 3.0f;
    float b[9];
#pragma unroll
    for (int i = 0; i < 9; i++) {
        float t0 = (i - 3) * h - 1.0f;
        float t1 = (i - 2) * h - 1.0f;
        b[i] = (v >= t0 && v < t1) ? 1.0f : 0.0f;
    }
#pragma unroll
    for (int j = 1; j <= 3; j++) {
        float inv = 1.0f / (j * h);
#pragma unroll
        for (int i = 0; i + j < 9; i++) {
            float ti  = (i - 3) * h - 1.0f;
            float tj1 = (i + j - 2) * h - 1.0f;
            b[i] = (v - ti) * inv * b[i] + (tj1 - v) * inv * b[i + 1];
        }
    }
    phi[0] = v / (1.0f + __expf(-v));
#pragma unroll
    for (int g = 0; g < 6; g++) phi[g + 1] = b[g];
}

// ---------------- prep: fold scaler into [o][c][g][12] ----------------
template <int O, int C>
__device__ __forceinline__ void fold_w(float* Wd, int i, const float* __restrict__ bw,
                                       const float* __restrict__ sw, const float* __restrict__ sc) {
    int kp = i % 12;
    int g  = (i / 12) % 7;
    int c  = (i / 84) % C;
    int o  = i / (84 * C);
    float val = 0.0f;
    if (kp < 9) {
        int f = c * 9 + kp;
        constexpr int F = C * 9;
        val = (g == 0) ? bw[o * F + f] : sw[(o * F + f) * 6 + (g - 1)] * sc[o * F + f];
    }
    Wd[i] = val;
}

#define NPREP (2016 + 10752 + 43008)

__global__ void prep_all(
    const float* __restrict__ c1bw, const float* __restrict__ c1sw, const float* __restrict__ c1sc,
    const float* __restrict__ c2bw, const float* __restrict__ c2sw, const float* __restrict__ c2sc,
    const float* __restrict__ c3bw, const float* __restrict__ c3sw, const float* __restrict__ c3sc)
{
    int i = blockIdx.x * blockDim.x + threadIdx.x;
    if (i < 2016) {
        fold_w<8, 3>(g_W1, i, c1bw, c1sw, c1sc);
    } else if (i < 2016 + 10752) {
        fold_w<16, 8>(g_W2, i - 2016, c2bw, c2sw, c2sc);
    } else if (i < NPREP) {
        fold_w<32, 16>(g_W3, i - 12768, c3bw, c3sw, c3sc);
    }
}

// ---------------- generic conv inner loop over CT channels ----------------
template <int CT, int OT, int Yd, int Xd>
__device__ __forceinline__ void conv_body(
    const float* E, const float* __restrict__ Wg, float acc[OT][4],
    int c0, int pr, int px, int og_base, int C_total)
{
#pragma unroll 1
    for (int cc = 0; cc < CT; cc++) {
        int c = c0 + cc;
#pragma unroll
        for (int g = 0; g < 7; g++) {
            float e[4][4];
            const int base = ((c * Yd + 2 * pr) * 7 + g) * Xd + 2 * px;
#pragma unroll
            for (int dy = 0; dy < 4; dy++) {
                const float2* r = reinterpret_cast<const float2*>(&E[base + dy * 7 * Xd]);
                float2 a = r[0], b2 = r[1];
                e[dy][0] = a.x; e[dy][1] = a.y; e[dy][2] = b2.x; e[dy][3] = b2.y;
            }
#pragma unroll
            for (int o = 0; o < OT; o++) {
                const float4* wv = reinterpret_cast<const float4*>(
                    &Wg[(((og_base + o * C_total) + c) * 7 + g) * 12]);
                float4 w0 = __ldg(&wv[0]);
                float4 w1 = __ldg(&wv[1]);
                float4 w2 = __ldg(&wv[2]);
                float wk[9] = {w0.x, w0.y, w0.z, w0.w, w1.x, w1.y, w1.z, w1.w, w2.x};
#pragma unroll
                for (int kh = 0; kh < 3; kh++)
#pragma unroll
                    for (int kw = 0; kw < 3; kw++) {
                        float wgt = wk[kh * 3 + kw];
                        acc[o][0] += e[kh][kw] * wgt;
                        acc[o][1] += e[kh][kw + 1] * wgt;
                        acc[o][2] += e[kh + 1][kw] * wgt;
                        acc[o][3] += e[kh + 1][kw + 1] * wgt;
                    }
            }
        }
    }
}

// ---------------- phi expansion of a strip into smem ----------------
template <int C, int H, int W, int SR, int THREADS>
__device__ __forceinline__ void expand_strip(
    const float* __restrict__ inb, float* E, int s, int tid)
{
    constexpr int Yd = 2 * SR + 2, Xd = W + 2;
    const int gy0 = 2 * s * SR - 1;
    for (int i = tid; i < C * Yd * Xd; i += THREADS) {
        int x  = i % Xd;
        int ly = (i / Xd) % Yd;
        int c  = i / (Xd * Yd);
        int gy = gy0 + ly;
        float v = 0.0f;
        if (gy >= 0 && gy < H && x >= 1 && x <= W) v = __ldg(&inb[(c * H + gy) * W + x - 1]);
        float phi[7];
        compute_phi(v, phi);
#pragma unroll
        for (int g = 0; g < 7; g++) E[((c * Yd + ly) * 7 + g) * Xd + x] = phi[g];
    }
}

// ---------------- layers 1/2: strip kernel, 64 threads ----------------
template <int C, int H, int W, int O, int OT, int SR>
__global__ void __launch_bounds__(64, 8) kan_layer(
    const float* __restrict__ in, float* __restrict__ out, const float* __restrict__ Wg)
{
    constexpr int PW = W / 2, PH = H / 2;
    constexpr int OG = O / OT;
    constexpr int STRIPS = PH / SR;
    constexpr int Yd = 2 * SR + 2, Xd = W + 2;
    constexpr int THREADS = PW * SR * OG;
    static_assert(THREADS == 64, "block must be 64 threads");

    extern __shared__ float E[];

    const int b   = blockIdx.x / STRIPS;
    const int s   = blockIdx.x % STRIPS;
    const int tid = threadIdx.x;

    expand_strip<C, H, W, SR, THREADS>(in + (size_t)b * C * H * W, E, s, tid);
    __syncthreads();

    const int px = tid % PW;
    const int pr = (tid / PW) % SR;
    const int og = tid / (PW * SR);

    float acc[OT][4];
#pragma unroll
    for (int o = 0; o < OT; o++) acc[o][0] = acc[o][1] = acc[o][2] = acc[o][3] = 0.0f;

    conv_body<C, OT, Yd, Xd>(E, Wg, acc, 0, pr, px, og * OT * C, C);

    float* outb = out + (size_t)b * O * PH * PW;
    const int prow = s * SR + pr;
#pragma unroll
    for (int o = 0; o < OT; o++) {
        float m = fmaxf(fmaxf(acc[o][0], acc[o][1]), fmaxf(acc[o][2], acc[o][3]));
        outb[((og * OT + o) * PH + prow) * PW + px] = m;
    }
}

// ---------------- layer 3: channel-split (CS=4), SR=1, 128 threads ----------------
// thread = (px, og, cs); cs>=1 writes partials to smem, cs=0 combines + pools.
__global__ void __launch_bounds__(128, 4) kan_layer3(
    const float* __restrict__ in, float* __restrict__ out, const float* __restrict__ Wg)
{
    constexpr int C = 16, H = 8, W = 8, O = 32, OT = 4, SR = 1;
    constexpr int PW = W / 2, PH = H / 2;
    constexpr int OG = O / OT;                 // 8
    constexpr int STRIPS = PH / SR;            // 4
    constexpr int Yd = 2 * SR + 2, Xd = W + 2; // 4, 10
    constexpr int THREADS = 128;

    extern __shared__ float E[];               // 16*4*7*10 = 4480 floats

    const int b   = blockIdx.x / STRIPS;
    const int s   = blockIdx.x % STRIPS;
    const int tid = threadIdx.x;

    expand_strip<C, H, W, SR, THREADS>(in + (size_t)b * C * H * W, E, s, tid);
    __syncthreads();

    // 128 threads = PW(4) * OG(8) * CS(4); each cs owns 4 input channels
    const int px = tid % PW;
    const int og = (tid / PW) % OG;
    const int cs = tid / (PW * OG);            // 0..3

    float acc[OT][4];
#pragma unroll
    for (int o = 0; o < OT; o++) acc[o][0] = acc[o][1] = acc[o][2] = acc[o][3] = 0.0f;

    conv_body<4, OT, Yd, Xd>(E, Wg, acc, cs * 4, 0, px, og * OT * C, C);

    __syncthreads();                            // all conv reads of E done
    float* P = E;                               // reuse arena: 3 * 32 * 17 floats
    const int slot = tid % (PW * OG);           // same (px,og) across cs
    if (cs >= 1) {
#pragma unroll
        for (int o = 0; o < OT; o++)
#pragma unroll
            for (int k = 0; k < 4; k++)
                P[((cs - 1) * (PW * OG) + slot) * 17 + o * 4 + k] = acc[o][k];
    }
    __syncthreads();
    if (cs == 0) {
        float* outb = out + (size_t)b * O * PH * PW;
        const int prow = s;
#pragma unroll
        for (int o = 0; o < OT; o++) {
            float v0 = acc[o][0], v1 = acc[o][1], v2 = acc[o][2], v3 = acc[o][3];
#pragma unroll
            for (int q = 0; q < 3; q++) {
                v0 += P[(q * (PW * OG) + slot) * 17 + o * 4 + 0];
                v1 += P[(q * (PW * OG) + slot) * 17 + o * 4 + 1];
                v2 += P[(q * (PW * OG) + slot) * 17 + o * 4 + 2];
                v3 += P[(q * (PW * OG) + slot) * 17 + o * 4 + 3];
            }
            float m = fmaxf(fmaxf(v0, v1), fmaxf(v2, v3));
            outb[((og * OT + o) * PH + prow) * PW + px] = m;
        }
    }
}

// ---------------- final linear 512 -> 100 (direct linw rows, float4) ----------------
__global__ void __launch_bounds__(128) linear_k(const float* __restrict__ linw,
                                                const float* __restrict__ bias,
                                                float* __restrict__ out) {
    __shared__ float hs[512];
    int b = blockIdx.x;
    for (int i = threadIdx.x; i < 512; i += 128) hs[i] = g_out3[b * 512 + i];
    __syncthreads();
    int j = threadIdx.x;
    if (j < 100) {
        float a = __ldg(&bias[j]);
        const float4* wr = reinterpret_cast<const float4*>(linw + (size_t)j * 512);
        const float4* h4 = reinterpret_cast<const float4*>(hs);
#pragma unroll 8
        for (int f = 0; f < 128; f++) {
            float4 w = __ldg(&wr[f]);
            float4 hv = h4[f];
            a += w.x * hv.x + w.y * hv.y + w.z * hv.z + w.w * hv.w;
        }
        out[(size_t)b * 100 + j] = a;
    }
}

extern "C" void kernel_launch(void* const* d_in, const int* in_sizes, int n_in,
                              void* d_out, int out_size) {
    const float* x     = (const float*)d_in[0];
    const float* c1bw  = (const float*)d_in[1];
    const float* c1sw  = (const float*)d_in[2];
    const float* c1sc  = (const float*)d_in[3];
    const float* c2bw  = (const float*)d_in[4];
    const float* c2sw  = (const float*)d_in[5];
    const float* c2sc  = (const float*)d_in[6];
    const float* c3bw  = (const float*)d_in[7];
    const float* c3sw  = (const float*)d_in[8];
    const float* c3sc  = (const float*)d_in[9];
    const float* linw  = (const float*)d_in[10];
    const float* linb  = (const float*)d_in[11];
    float* out = (float*)d_out;

    static float *p_W1, *p_W2, *p_W3, *p_o1, *p_o2, *p_o3;
    static bool init = false;
    if (!init) {
        cudaGetSymbolAddress((void**)&p_W1, g_W1);
        cudaGetSymbolAddress((void**)&p_W2, g_W2);
        cudaGetSymbolAddress((void**)&p_W3, g_W3);
        cudaGetSymbolAddress((void**)&p_o1, g_out1);
        cudaGetSymbolAddress((void**)&p_o2, g_out2);
        cudaGetSymbolAddress((void**)&p_o3, g_out3);
        init = true;
    }

    prep_all<<<(NPREP + 255) / 256, 256>>>(c1bw, c1sw, c1sc, c2bw, c2sw, c2sc,
                                           c3bw, c3sw, c3sc);

    // L1: C=3 O=8  OT=4 SR=2 -> 64 thr (16*2*2), 8 strips, grid 2048, smem 17136 B
    kan_layer<3, 32, 32, 8, 4, 2><<<BATCH * 8, 64, 3 * 6 * 7 * 34 * 4>>>(x, p_o1, p_W1);
    // L2: C=8 O=16 OT=2 SR=1 -> 64 thr (8*1*8), 8 strips, grid 2048, smem 8*4*7*18*4 = 16128 B
    kan_layer<8, 16, 16, 16, 2, 1><<<BATCH * 8, 64, 8 * 4 * 7 * 18 * 4>>>(p_o1, p_o2, p_W2);
    // L3: C=16 O=32 OT=4 SR=1 CS=4 -> 128 thr, 4 strips, grid 1024, smem 16*4*7*10*4 = 17920 B
    kan_layer3<<<BATCH * 4, 128, 16 * 4 * 7 * 10 * 4>>>(p_o2, p_o3, p_W3);

    linear_k<<<BATCH, 128>>>(linw, linb, out);
}